// round 10
// baseline (speedup 1.0000x reference)
#include <cuda_runtime.h>
#include <cuda_bf16.h>
#include <cstdint>

#define BATCH 4
#define NPIX  4096
#define CDIM  256
#define NPTOT (BATCH * NPIX)

// Scratch (__device__ globals; allocation-free rule)
__device__ __nv_bfloat16 g_wb [320 * 256];                  // weights bf16
__device__ __nv_bfloat16 g_xb [(size_t)NPTOT * 256];        // xp bf16
__device__ __nv_bfloat16 g_q32[(size_t)NPTOT * 32];         // q bf16
__device__ __nv_bfloat16 g_k32[(size_t)NPTOT * 32];         // k bf16
__device__ __nv_bfloat16 g_v  [(size_t)NPTOT * CDIM];       // V [pg][c] bf16
__device__ __nv_bfloat16 g_P  [(size_t)BATCH * NPIX * NPIX];// e^(E-40) bf16
__device__ float         g_l  [NPTOT];                      // row sums
__device__ float         g_o  [(size_t)BATCH * CDIM * NPIX];// O transposed [b][c][n]

// ---------------- helpers ----------------
__device__ __forceinline__ uint32_t s2u(const void* p) {
    uint32_t a;
    asm("{ .reg .u64 t; cvta.to.shared.u64 t, %1; cvt.u32.u64 %0, t; }" : "=r"(a) : "l"(p));
    return a;
}
// packs (e0, e1) -> bf16x2 word, e0 in low half
__device__ __forceinline__ uint32_t packbf(float e0, float e1) {
    uint32_t r;
    asm("cvt.rn.satfinite.bf16x2.f32 %0, %1, %2;" : "=r"(r) : "f"(e1), "f"(e0));
    return r;
}
__device__ __forceinline__ void ldsm4(uint32_t* r, uint32_t a) {
    asm volatile("ldmatrix.sync.aligned.m8n8.x4.shared.b16 {%0,%1,%2,%3}, [%4];"
                 : "=r"(r[0]), "=r"(r[1]), "=r"(r[2]), "=r"(r[3]) : "r"(a));
}
__device__ __forceinline__ void ldsm4t(uint32_t* r, uint32_t a) {
    asm volatile("ldmatrix.sync.aligned.m8n8.x4.trans.shared.b16 {%0,%1,%2,%3}, [%4];"
                 : "=r"(r[0]), "=r"(r[1]), "=r"(r[2]), "=r"(r[3]) : "r"(a));
}
__device__ __forceinline__ void mma16816(float* d, const uint32_t* a, uint32_t b0, uint32_t b1) {
    asm volatile("mma.sync.aligned.m16n8k16.row.col.f32.bf16.bf16.f32 "
                 "{%0,%1,%2,%3}, {%4,%5,%6,%7}, {%8,%9}, {%0,%1,%2,%3};"
                 : "+f"(d[0]), "+f"(d[1]), "+f"(d[2]), "+f"(d[3])
                 : "r"(a[0]), "r"(a[1]), "r"(a[2]), "r"(a[3]), "r"(b0), "r"(b1));
}
__device__ __forceinline__ void cpa16(uint32_t dst, const void* src) {
    asm volatile("cp.async.cg.shared.global [%0], [%1], 16;" :: "r"(dst), "l"(src) : "memory");
}
#define CP_COMMIT() asm volatile("cp.async.commit_group;" ::: "memory")

// ---------------------------------------------------------------------------
// Kernel 0: weight bf16 convert. o: 0..31 q, 32..63 k, 64..319 v.
// ---------------------------------------------------------------------------
__global__ __launch_bounds__(256) void wconv_kernel(
    const float* __restrict__ wq, const float* __restrict__ wk,
    const float* __restrict__ wv)
{
    #pragma unroll
    for (int i = 0; i < 4; i++) {
        int e = blockIdx.x * 1024 + i * 256 + threadIdx.x;
        int o = e >> 8, c = e & 255;
        const float* src = (o < 32) ? (wq + o * 256)
                         : (o < 64) ? (wk + (o - 32) * 256)
                                    : (wv + (o - 64) * 256);
        g_wb[e] = __float2bfloat16(src[c]);
    }
}

// ---------------------------------------------------------------------------
// Kernel 1: space-to-depth gather -> xp bf16 [pg][256]; zero g_l.
// ---------------------------------------------------------------------------
__global__ __launch_bounds__(256) void gather_kernel(const float* __restrict__ x)
{
    __shared__ float xs[32][260];
    const int whalf = blockIdx.x, h2 = blockIdx.y, b = blockIdx.z;
    const int t = threadIdx.x;

    int gid = (((b * 64 + h2) * 2 + whalf) << 8) + t;
    if (gid < NPTOT) g_l[gid] = 0.0f;

    #pragma unroll
    for (int i = 0; i < 32; i++) {
        int idx = i * 256 + t;
        int row = idx >> 6, j = idx & 63;
        int ci = row & 63, hi = row >> 6;
        float val = x[(((size_t)(b * 64 + ci) * 128) + (2 * h2 + hi)) * 128 + whalf * 64 + j];
        xs[j >> 1][(j & 1) * 128 + hi * 64 + ci] = val;
    }
    __syncthreads();

    const int p = t >> 3, cg = t & 7;
    const size_t pg = (size_t)b * NPIX + h2 * 64 + whalf * 32 + p;
    uint32_t* dh = (uint32_t*)(g_xb + pg * 256);
    #pragma unroll
    for (int i = 0; i < 16; i++) {
        int u = cg + i * 8;
        dh[u] = packbf(xs[p][u * 2], xs[p][u * 2 + 1]);
    }
}

// ---------------------------------------------------------------------------
// Kernel 2: projections, plain bf16 HMMA. CTA 128 px x 64 out, K=256/32.
// ---------------------------------------------------------------------------
#define PG_AS   40
#define PG_ABUF (128 * PG_AS)
#define PG_BBUF (64 * PG_AS)
#define PG_STAGE (PG_ABUF + PG_BBUF)
#define PG_SMEM (2 * PG_STAGE * 2)       // 30720 bytes

__global__ __launch_bounds__(256, 3) void projgemm_kernel(
    const float* __restrict__ bq, const float* __restrict__ bk,
    const float* __restrict__ bv)
{
    extern __shared__ __nv_bfloat16 pgs[];
    const int ptile = blockIdx.x, otile = blockIdx.y;
    const int t = threadIdx.x, lane = t & 31, wid = t >> 5;
    const int warp_r = wid >> 2, warp_o = wid & 3;

    auto issue = [&](int kc, int s) {
        __nv_bfloat16* A = pgs + s * PG_STAGE;
        __nv_bfloat16* B = A + PG_ABUF;
        #pragma unroll
        for (int i = 0; i < 2; i++) {
            int idx = i * 256 + t;
            int row = idx >> 2, c16 = idx & 3;
            cpa16(s2u(A + row * PG_AS + c16 * 8),
                  g_xb + (size_t)(ptile * 128 + row) * 256 + kc * 32 + c16 * 8);
        }
        {
            int row = t >> 2, c16 = t & 3;
            cpa16(s2u(B + row * PG_AS + c16 * 8),
                  g_wb + (size_t)(otile * 64 + row) * 256 + kc * 32 + c16 * 8);
        }
        CP_COMMIT();
    };

    float acc[4][2][4];
    #pragma unroll
    for (int mi = 0; mi < 4; mi++)
        #pragma unroll
        for (int ni = 0; ni < 2; ni++)
            #pragma unroll
            for (int i = 0; i < 4; i++) acc[mi][ni][i] = 0.0f;

    issue(0, 0);
    for (int kc = 0; kc < 8; kc++) {
        if (kc < 7) issue(kc + 1, (kc + 1) & 1);
        if (kc < 7) asm volatile("cp.async.wait_group 1;" ::: "memory");
        else        asm volatile("cp.async.wait_group 0;" ::: "memory");
        __syncthreads();
        __nv_bfloat16* A = pgs + (kc & 1) * PG_STAGE;
        __nv_bfloat16* B = A + PG_ABUF;
        #pragma unroll
        for (int k16 = 0; k16 < 2; k16++) {
            const int kb = k16 * 16 + ((lane >> 4) << 3);
            uint32_t Af[4][4], Bf[4];
            #pragma unroll
            for (int mi = 0; mi < 4; mi++)
                ldsm4(Af[mi], s2u(A + (warp_r * 64 + mi * 16 + (lane & 15)) * PG_AS + kb));
            ldsm4(Bf, s2u(B + (warp_o * 16 + (lane & 15)) * PG_AS + kb));
            #pragma unroll
            for (int mi = 0; mi < 4; mi++)
                #pragma unroll
                for (int ni = 0; ni < 2; ni++)
                    mma16816(acc[mi][ni], Af[mi], Bf[ni], Bf[ni + 2]);
        }
        __syncthreads();
    }

    // epilogue: add bias, route to q/k (bf16) or v (bf16)
    #pragma unroll
    for (int mi = 0; mi < 4; mi++) {
        int px = warp_r * 64 + mi * 16 + (lane >> 2);
        size_t pg0 = (size_t)ptile * 128 + px;
        size_t pg1 = pg0 + 8;
        #pragma unroll
        for (int ni = 0; ni < 2; ni++) {
            int c = warp_o * 16 + ni * 8 + (lane & 3) * 2;
            int o = otile * 64 + c;
            float b0, b1;
            if (o < 32)      { b0 = bq[o];      b1 = bq[o + 1]; }
            else if (o < 64) { b0 = bk[o - 32]; b1 = bk[o - 31]; }
            else             { b0 = bv[o - 64]; b1 = bv[o - 63]; }
            float v00 = acc[mi][ni][0] + b0, v01 = acc[mi][ni][1] + b1;
            float v10 = acc[mi][ni][2] + b0, v11 = acc[mi][ni][3] + b1;
            if (otile == 0) {
                uint32_t* dst = (o < 32) ? (uint32_t*)g_q32 : (uint32_t*)g_k32;
                int oo = (o & 31) >> 1;
                dst[pg0 * 16 + oo] = packbf(v00, v01);
                dst[pg1 * 16 + oo] = packbf(v10, v11);
            } else {
                int cv = o - 64;
                *(uint32_t*)(g_v + pg0 * 256 + cv) = packbf(v00, v01);
                *(uint32_t*)(g_v + pg1 * 256 + cv) = packbf(v10, v11);
            }
        }
    }
}

// ---------------------------------------------------------------------------
// Kernel 3: E = QK^T (plain bf16 HMMA, K=32) + fused exp(E-40) -> P, row sums
// from fp32 accumulators. CTA 128 n x 128 m, 8 warps 2x4.
// ---------------------------------------------------------------------------
#define EG_TS 40                                    // q/k tile row stride (bf16)
#define EG_SMEM_BF (128 * 136)                      // P stage dominates

__global__ __launch_bounds__(256, 2) void egemm_kernel()
{
    __shared__ __align__(16) __nv_bfloat16 esm[EG_SMEM_BF];  // tiles then P stage
    __nv_bfloat16* sQ = esm;
    __nv_bfloat16* sK = esm + 128 * EG_TS;
    const int m0 = blockIdx.x * 128, n0 = blockIdx.y * 128, b = blockIdx.z;
    const int t = threadIdx.x, lane = t & 31, wid = t >> 5;
    const int warp_r = wid >> 2, warp_c = wid & 3;

    {
        const uint4* qs = (const uint4*)(g_q32 + ((size_t)(b * NPIX + n0)) * 32);
        const uint4* ks = (const uint4*)(g_k32 + ((size_t)(b * NPIX + m0)) * 32);
        uint4* q4 = (uint4*)sQ;
        uint4* k4 = (uint4*)sK;
        #pragma unroll
        for (int i = 0; i < 2; i++) {
            int idx = i * 256 + t;
            int row = idx >> 2, ch = idx & 3;
            q4[row * 5 + ch] = qs[idx];
            k4[row * 5 + ch] = ks[idx];
        }
    }
    __syncthreads();

    float acc[4][4][4];
    #pragma unroll
    for (int mi = 0; mi < 4; mi++)
        #pragma unroll
        for (int ni = 0; ni < 4; ni++)
            #pragma unroll
            for (int i = 0; i < 4; i++) acc[mi][ni][i] = 0.0f;

    #pragma unroll
    for (int k16 = 0; k16 < 2; k16++) {
        const int kb = k16 * 16 + ((lane >> 4) << 3);
        uint32_t A[4][4];
        #pragma unroll
        for (int mi = 0; mi < 4; mi++)
            ldsm4(A[mi], s2u(sQ + (warp_r * 64 + mi * 16 + (lane & 15)) * EG_TS + kb));
        uint32_t Bm[2][4];
        #pragma unroll
        for (int nj = 0; nj < 2; nj++)
            ldsm4(Bm[nj], s2u(sK + (warp_c * 32 + nj * 16 + (lane & 15)) * EG_TS + kb));
        #pragma unroll
        for (int mi = 0; mi < 4; mi++)
            #pragma unroll
            for (int ni = 0; ni < 4; ni++) {
                int nj = ni >> 1, s = ni & 1;
                mma16816(acc[mi][ni], A[mi], Bm[nj][s], Bm[nj][s + 2]);
            }
    }
    __syncthreads();   // tiles dead; reuse esm as P stage (stride 136)

    __nv_bfloat16* sS = esm;
    #pragma unroll
    for (int mi = 0; mi < 4; mi++) {
        int r0 = warp_r * 64 + mi * 16 + (lane >> 2);
        float s0 = 0.0f, s1 = 0.0f;
        #pragma unroll
        for (int ni = 0; ni < 4; ni++) {
            int c = warp_c * 32 + ni * 8 + (lane & 3) * 2;
            float p00 = __expf(acc[mi][ni][0] - 40.0f);
            float p01 = __expf(acc[mi][ni][1] - 40.0f);
            float p10 = __expf(acc[mi][ni][2] - 40.0f);
            float p11 = __expf(acc[mi][ni][3] - 40.0f);
            s0 += p00 + p01;
            s1 += p10 + p11;
            *(uint32_t*)(sS + r0 * 136 + c)       = packbf(p00, p01);
            *(uint32_t*)(sS + (r0 + 8) * 136 + c) = packbf(p10, p11);
        }
        // reduce over the 4 lanes sharing each row (lane&3 varies c)
        s0 += __shfl_xor_sync(0xffffffffu, s0, 1);
        s0 += __shfl_xor_sync(0xffffffffu, s0, 2);
        s1 += __shfl_xor_sync(0xffffffffu, s1, 1);
        s1 += __shfl_xor_sync(0xffffffffu, s1, 2);
        if ((lane & 3) == 0) {
            atomicAdd(&g_l[b * NPIX + n0 + r0], s0);
            atomicAdd(&g_l[b * NPIX + n0 + r0 + 8], s1);
        }
    }
    __syncthreads();

    // coalesced P write (pure copy)
    #pragma unroll
    for (int pass = 0; pass < 4; pass++) {
        int row = pass * 32 + (t >> 3), ch = t & 7;
        const uint4* srow = (const uint4*)(sS + row * 136);
        uint4* drow = (uint4*)(g_P + ((size_t)(b * NPIX + n0 + row)) * NPIX + m0);
        drow[ch * 2]     = srow[ch * 2];
        drow[ch * 2 + 1] = srow[ch * 2 + 1];
    }
}

// ---------------------------------------------------------------------------
// Kernel 4: O = P @ V (bf16 HMMA, cp.async double buffer), output [b][c][n].
// ---------------------------------------------------------------------------
#define PBUF (128 * 72)
#define VBUF (64 * 264)
#define BUFBF (PBUF + VBUF)
#define PV_SMEM (2 * BUFBF * 2)

__global__ __launch_bounds__(256, 1) void pv_kernel()
{
    extern __shared__ __align__(16) __nv_bfloat16 pvs[];
    const int n0 = blockIdx.x * 128, b = blockIdx.y;
    const int t = threadIdx.x, lane = t & 31, wid = t >> 5;
    const int warp_r = wid >> 2, warp_c = wid & 3;

    const __nv_bfloat16* pbase = g_P + ((size_t)(b * NPIX + n0)) * NPIX;
    const __nv_bfloat16* vbase = g_v + (size_t)b * NPIX * CDIM;

    float acc[4][8][4];
    #pragma unroll
    for (int mi = 0; mi < 4; mi++)
        #pragma unroll
        for (int ni = 0; ni < 8; ni++)
            #pragma unroll
            for (int i = 0; i < 4; i++) acc[mi][ni][i] = 0.0f;

    auto issue = [&](int ch, int s) {
        __nv_bfloat16* sP = pvs + s * BUFBF;
        __nv_bfloat16* sV = sP + PBUF;
        #pragma unroll
        for (int i = 0; i < 4; i++) {
            int idx = i * 256 + t;
            int row = idx >> 3, c8 = idx & 7;
            cpa16(s2u(sP + row * 72 + c8 * 8),
                  pbase + (size_t)row * NPIX + ch * 64 + c8 * 8);
        }
        #pragma unroll
        for (int i = 0; i < 8; i++) {
            int idx = i * 256 + t;
            int row = idx >> 5, c8 = idx & 31;
            cpa16(s2u(sV + row * 264 + c8 * 8),
                  vbase + (size_t)(ch * 64 + row) * CDIM + c8 * 8);
        }
        CP_COMMIT();
    };

    issue(0, 0);
    for (int ch = 0; ch < 64; ch++) {
        if (ch < 63) issue(ch + 1, (ch + 1) & 1);
        if (ch < 63) asm volatile("cp.async.wait_group 1;" ::: "memory");
        else         asm volatile("cp.async.wait_group 0;" ::: "memory");
        __syncthreads();
        __nv_bfloat16* sP = pvs + (ch & 1) * BUFBF;
        __nv_bfloat16* sV = sP + PBUF;
        #pragma unroll
        for (int k16 = 0; k16 < 4; k16++) {
            const int kb = k16 * 16;
            uint32_t A[4][4];
            #pragma unroll
            for (int mi = 0; mi < 4; mi++)
                ldsm4(A[mi], s2u(sP + (warp_r * 64 + mi * 16 + (lane & 15)) * 72
                                    + kb + ((lane >> 4) << 3)));
            uint32_t Bm[4][4];
            #pragma unroll
            for (int nj = 0; nj < 4; nj++) {
                int k = kb + (lane & 7) + ((lane >> 4) << 3);
                int n = warp_c * 64 + nj * 16 + ((lane >> 3) & 1) * 8;
                ldsm4t(Bm[nj], s2u(sV + k * 264 + n));
            }
            #pragma unroll
            for (int mi = 0; mi < 4; mi++)
                #pragma unroll
                for (int ni = 0; ni < 8; ni++) {
                    int nj = ni >> 1, s = ni & 1;
                    mma16816(acc[mi][ni], A[mi], Bm[nj][s], Bm[nj][s + 2]);
                }
        }
        __syncthreads();
    }

    // epilogue: normalize, transpose via smem, write g_o[b][c][n] coalesced
    float* sT = (float*)pvs;   // [128 c][140 px-stride]
    #pragma unroll
    for (int half = 0; half < 2; half++) {
        if ((warp_c >> 1) == half) {
            #pragma unroll
            for (int mi = 0; mi < 4; mi++) {
                int px0 = warp_r * 64 + mi * 16 + (lane >> 2);
                float li0 = 1.0f / g_l[b * NPIX + n0 + px0];
                float li1 = 1.0f / g_l[b * NPIX + n0 + px0 + 8];
                #pragma unroll
                for (int ni = 0; ni < 8; ni++) {
                    int cl = (warp_c & 1) * 64 + ni * 8 + (lane & 3) * 2;
                    sT[cl * 140 + px0]           = acc[mi][ni][0] * li0;
                    sT[(cl + 1) * 140 + px0]     = acc[mi][ni][1] * li0;
                    sT[cl * 140 + px0 + 8]       = acc[mi][ni][2] * li1;
                    sT[(cl + 1) * 140 + px0 + 8] = acc[mi][ni][3] * li1;
                }
            }
        }
        __syncthreads();
        #pragma unroll
        for (int i = 0; i < 16; i++) {
            int f4 = i * 256 + t;
            int c = f4 >> 5, col = (f4 & 31) * 4;
            float4 v = *(float4*)(sT + c * 140 + col);
            *(float4*)(g_o + ((size_t)(b * 256 + half * 128 + c)) * 4096 + n0 + col) = v;
        }
        __syncthreads();
    }
}

// ---------------------------------------------------------------------------
// Kernel 5: epilogue gamma*O + xp, depth-to-space (g_o reads coalesced).
// ---------------------------------------------------------------------------
__global__ __launch_bounds__(256) void epi_kernel(
    const float* __restrict__ x, const float* __restrict__ gamma,
    float* __restrict__ out)
{
    int idx = blockIdx.x * 256 + threadIdx.x;
    int w = idx & 127, h = (idx >> 7) & 127, ci = (idx >> 14) & 63, b = idx >> 20;
    int CC = (w & 1) * 128 + (h & 1) * 64 + ci;
    int n = (h >> 1) * 64 + (w >> 1);
    out[idx] = __ldg(gamma) * g_o[((size_t)(b * 256 + CC)) * 4096 + n] + x[idx];
}

// ---------------------------------------------------------------------------
extern "C" void kernel_launch(void* const* d_in, const int* in_sizes, int n_in,
                              void* d_out, int out_size)
{
    const float* x     = (const float*)d_in[0];
    const float* wq    = (const float*)d_in[1];
    const float* bq    = (const float*)d_in[2];
    const float* wk    = (const float*)d_in[3];
    const float* bk    = (const float*)d_in[4];
    const float* wv    = (const float*)d_in[5];
    const float* bv    = (const float*)d_in[6];
    const float* gamma = (const float*)d_in[7];
    float* out = (float*)d_out;
    (void)in_sizes; (void)n_in; (void)out_size;

    cudaFuncSetAttribute(projgemm_kernel, cudaFuncAttributeMaxDynamicSharedMemorySize, PG_SMEM);
    cudaFuncSetAttribute(pv_kernel,       cudaFuncAttributeMaxDynamicSharedMemorySize, PV_SMEM);

    wconv_kernel<<<80, 256>>>(wq, wk, wv);

    dim3 ggrid(2, 64, BATCH);
    gather_kernel<<<ggrid, 256>>>(x);

    dim3 pggrid(NPTOT / 128, 5);
    projgemm_kernel<<<pggrid, 256, PG_SMEM>>>(bq, bk, bv);

    dim3 egrid(NPIX / 128, NPIX / 128, BATCH);
    egemm_kernel<<<egrid, 256>>>();

    dim3 vgrid(NPIX / 128, BATCH);
    pv_kernel<<<vgrid, 256, PV_SMEM>>>();

    epi_kernel<<<(BATCH * 64 * 128 * 128) / 256, 256>>>(x, gamma, out);
}

// round 11
// speedup vs baseline: 1.6248x; 1.6248x over previous
#include <cuda_runtime.h>
#include <cuda_bf16.h>
#include <cstdint>

#define BATCH 4
#define NPIX  4096
#define CDIM  256
#define NPTOT (BATCH * NPIX)   // 16384 pixels total

// Scratch (__device__ globals; allocation-free rule)
__device__ __nv_bfloat16 g_wh [320 * 256];                  // weights hi
__device__ __nv_bfloat16 g_wl [320 * 256];                  // weights lo
__device__ __nv_bfloat16 g_xh [(size_t)NPTOT * 256];        // xp hi
__device__ __nv_bfloat16 g_xl [(size_t)NPTOT * 256];        // xp lo
__device__ __nv_bfloat16 g_q64[(size_t)NPTOT * 64];         // [qh(32)|ql(32)]
__device__ __nv_bfloat16 g_k64[(size_t)NPTOT * 64];         // [kh(32)|kl(32)]
__device__ __nv_bfloat16 g_v  [(size_t)NPTOT * CDIM];       // V [pg][c] bf16
__device__ __nv_bfloat16 g_P  [(size_t)BATCH * NPIX * NPIX];// e^(E-40) bf16
__device__ float         g_l  [NPTOT];                      // row sums
__device__ float         g_o  [(size_t)BATCH * CDIM * NPIX];// O transposed [b][c][n]

// ---------------- helpers ----------------
__device__ __forceinline__ uint32_t s2u(const void* p) {
    uint32_t a;
    asm("{ .reg .u64 t; cvta.to.shared.u64 t, %1; cvt.u32.u64 %0, t; }" : "=r"(a) : "l"(p));
    return a;
}
// packs (e0, e1) -> bf16x2 word, e0 in low half
__device__ __forceinline__ uint32_t packbf(float e0, float e1) {
    uint32_t r;
    asm("cvt.rn.satfinite.bf16x2.f32 %0, %1, %2;" : "=r"(r) : "f"(e1), "f"(e0));
    return r;
}
__device__ __forceinline__ void ldsm4(uint32_t* r, uint32_t a) {
    asm volatile("ldmatrix.sync.aligned.m8n8.x4.shared.b16 {%0,%1,%2,%3}, [%4];"
                 : "=r"(r[0]), "=r"(r[1]), "=r"(r[2]), "=r"(r[3]) : "r"(a));
}
__device__ __forceinline__ void ldsm4t(uint32_t* r, uint32_t a) {
    asm volatile("ldmatrix.sync.aligned.m8n8.x4.trans.shared.b16 {%0,%1,%2,%3}, [%4];"
                 : "=r"(r[0]), "=r"(r[1]), "=r"(r[2]), "=r"(r[3]) : "r"(a));
}
__device__ __forceinline__ void mma16816(float* d, const uint32_t* a, uint32_t b0, uint32_t b1) {
    asm volatile("mma.sync.aligned.m16n8k16.row.col.f32.bf16.bf16.f32 "
                 "{%0,%1,%2,%3}, {%4,%5,%6,%7}, {%8,%9}, {%0,%1,%2,%3};"
                 : "+f"(d[0]), "+f"(d[1]), "+f"(d[2]), "+f"(d[3])
                 : "r"(a[0]), "r"(a[1]), "r"(a[2]), "r"(a[3]), "r"(b0), "r"(b1));
}
__device__ __forceinline__ void cpa16(uint32_t dst, const void* src) {
    asm volatile("cp.async.cg.shared.global [%0], [%1], 16;" :: "r"(dst), "l"(src) : "memory");
}
#define CP_COMMIT() asm volatile("cp.async.commit_group;" ::: "memory")

// ---------------------------------------------------------------------------
// Kernel 0: weight hi/lo split (one-time, tiny)
// ---------------------------------------------------------------------------
__global__ __launch_bounds__(256) void wconv_kernel(
    const float* __restrict__ wq, const float* __restrict__ wk,
    const float* __restrict__ wv)
{
    #pragma unroll
    for (int i = 0; i < 4; i++) {
        int e = blockIdx.x * 1024 + i * 256 + threadIdx.x;
        int o = e >> 8, c = e & 255;
        const float* src = (o < 32) ? (wq + o * 256)
                         : (o < 64) ? (wk + (o - 32) * 256)
                                    : (wv + (o - 64) * 256);
        float v = src[c];
        float h = __bfloat162float(__float2bfloat16(v));
        g_wh[e] = __float2bfloat16(v);
        g_wl[e] = __float2bfloat16(v - h);
    }
}

// ---------------------------------------------------------------------------
// Kernel 1: space-to-depth gather, emit xp bf16 hi/lo; zero g_l.
// ---------------------------------------------------------------------------
__global__ __launch_bounds__(256) void gather_kernel(const float* __restrict__ x)
{
    __shared__ float xs[32][260];
    const int whalf = blockIdx.x, h2 = blockIdx.y, b = blockIdx.z;
    const int t = threadIdx.x;

    int gid = (((b * 64 + h2) * 2 + whalf) << 8) + t;
    if (gid < NPTOT) g_l[gid] = 0.0f;

    #pragma unroll
    for (int i = 0; i < 32; i++) {
        int idx = i * 256 + t;
        int row = idx >> 6, j = idx & 63;
        int ci = row & 63, hi = row >> 6;
        float val = x[(((size_t)(b * 64 + ci) * 128) + (2 * h2 + hi)) * 128 + whalf * 64 + j];
        xs[j >> 1][(j & 1) * 128 + hi * 64 + ci] = val;
    }
    __syncthreads();

    const int p = t >> 3, cg = t & 7;
    const size_t pg = (size_t)b * NPIX + h2 * 64 + whalf * 32 + p;
    uint32_t* dh = (uint32_t*)(g_xh + pg * 256);
    uint32_t* dl = (uint32_t*)(g_xl + pg * 256);
    #pragma unroll
    for (int i = 0; i < 16; i++) {
        int u = cg + i * 8;
        float v0 = xs[p][u * 2], v1 = xs[p][u * 2 + 1];
        float h0 = __bfloat162float(__float2bfloat16(v0));
        float h1 = __bfloat162float(__float2bfloat16(v1));
        dh[u] = packbf(h0, h1);
        dl[u] = packbf(v0 - h0, v1 - h1);
    }
}

// ---------------------------------------------------------------------------
// Kernel 2: projections as compensated bf16 HMMA GEMM (unchanged from R9).
// ---------------------------------------------------------------------------
#define PG_AS   40
#define PG_ABUF (128 * PG_AS)
#define PG_BBUF (64 * PG_AS)
#define PG_STAGE (2 * PG_ABUF + 2 * PG_BBUF)
#define PG_SMEM (2 * PG_STAGE * 2)       // 61440 bytes

__global__ __launch_bounds__(256, 2) void projgemm_kernel(
    const float* __restrict__ bq, const float* __restrict__ bk,
    const float* __restrict__ bv)
{
    extern __shared__ __nv_bfloat16 pgs[];
    const int ptile = blockIdx.x, otile = blockIdx.y;
    const int t = threadIdx.x, lane = t & 31, wid = t >> 5;
    const int warp_r = wid >> 2, warp_o = wid & 3;

    auto issue = [&](int kc, int s) {
        __nv_bfloat16* Ah = pgs + s * PG_STAGE;
        __nv_bfloat16* Al = Ah + PG_ABUF;
        __nv_bfloat16* Bh = Al + PG_ABUF;
        __nv_bfloat16* Bl = Bh + PG_BBUF;
        #pragma unroll
        for (int i = 0; i < 2; i++) {
            int idx = i * 256 + t;
            int row = idx >> 2, c16 = idx & 3;
            size_t src = (size_t)(ptile * 128 + row) * 256 + kc * 32 + c16 * 8;
            cpa16(s2u(Ah + row * PG_AS + c16 * 8), g_xh + src);
            cpa16(s2u(Al + row * PG_AS + c16 * 8), g_xl + src);
        }
        {
            int row = t >> 2, c16 = t & 3;
            size_t src = (size_t)(otile * 64 + row) * 256 + kc * 32 + c16 * 8;
            cpa16(s2u(Bh + row * PG_AS + c16 * 8), g_wh + src);
            cpa16(s2u(Bl + row * PG_AS + c16 * 8), g_wl + src);
        }
        CP_COMMIT();
    };

    float acc[4][2][4];
    #pragma unroll
    for (int mi = 0; mi < 4; mi++)
        #pragma unroll
        for (int ni = 0; ni < 2; ni++)
            #pragma unroll
            for (int i = 0; i < 4; i++) acc[mi][ni][i] = 0.0f;

    issue(0, 0);
    for (int kc = 0; kc < 8; kc++) {
        if (kc < 7) issue(kc + 1, (kc + 1) & 1);
        if (kc < 7) asm volatile("cp.async.wait_group 1;" ::: "memory");
        else        asm volatile("cp.async.wait_group 0;" ::: "memory");
        __syncthreads();
        __nv_bfloat16* Ah = pgs + (kc & 1) * PG_STAGE;
        __nv_bfloat16* Al = Ah + PG_ABUF;
        __nv_bfloat16* Bh = Al + PG_ABUF;
        __nv_bfloat16* Bl = Bh + PG_BBUF;
        #pragma unroll
        for (int k16 = 0; k16 < 2; k16++) {
            const int kb = k16 * 16 + ((lane >> 4) << 3);
            uint32_t Ahf[4][4], Alf[4][4], Bhf[4], Blf[4];
            #pragma unroll
            for (int mi = 0; mi < 4; mi++) {
                int r = warp_r * 64 + mi * 16 + (lane & 15);
                ldsm4(Ahf[mi], s2u(Ah + r * PG_AS + kb));
                ldsm4(Alf[mi], s2u(Al + r * PG_AS + kb));
            }
            {
                int r = warp_o * 16 + (lane & 15);
                ldsm4(Bhf, s2u(Bh + r * PG_AS + kb));
                ldsm4(Blf, s2u(Bl + r * PG_AS + kb));
            }
            #pragma unroll
            for (int mi = 0; mi < 4; mi++)
                #pragma unroll
                for (int ni = 0; ni < 2; ni++) {
                    mma16816(acc[mi][ni], Ahf[mi], Bhf[ni], Bhf[ni + 2]);
                    mma16816(acc[mi][ni], Ahf[mi], Blf[ni], Blf[ni + 2]);
                    mma16816(acc[mi][ni], Alf[mi], Bhf[ni], Bhf[ni + 2]);
                }
        }
        __syncthreads();
    }

    // epilogue: add bias, route to q/k (hi/lo split) or v (bf16)
    #pragma unroll
    for (int mi = 0; mi < 4; mi++) {
        int px = warp_r * 64 + mi * 16 + (lane >> 2);
        size_t pg0 = (size_t)ptile * 128 + px;
        size_t pg1 = pg0 + 8;
        #pragma unroll
        for (int ni = 0; ni < 2; ni++) {
            int c = warp_o * 16 + ni * 8 + (lane & 3) * 2;
            int o = otile * 64 + c;
            float b0, b1;
            if (o < 32)      { b0 = bq[o];      b1 = bq[o + 1]; }
            else if (o < 64) { b0 = bk[o - 32]; b1 = bk[o - 31]; }
            else             { b0 = bv[o - 64]; b1 = bv[o - 63]; }
            float v00 = acc[mi][ni][0] + b0, v01 = acc[mi][ni][1] + b1;
            float v10 = acc[mi][ni][2] + b0, v11 = acc[mi][ni][3] + b1;
            if (otile == 0) {
                uint32_t* dst = (o < 32) ? (uint32_t*)g_q64 : (uint32_t*)g_k64;
                int oo = o & 31;
                float h00 = __bfloat162float(__float2bfloat16(v00));
                float h01 = __bfloat162float(__float2bfloat16(v01));
                float h10 = __bfloat162float(__float2bfloat16(v10));
                float h11 = __bfloat162float(__float2bfloat16(v11));
                dst[pg0 * 32 + (oo >> 1)]      = packbf(h00, h01);
                dst[pg0 * 32 + 16 + (oo >> 1)] = packbf(v00 - h00, v01 - h01);
                dst[pg1 * 32 + (oo >> 1)]      = packbf(h10, h11);
                dst[pg1 * 32 + 16 + (oo >> 1)] = packbf(v10 - h10, v11 - h11);
            } else {
                int cv = o - 64;
                *(uint32_t*)(g_v + pg0 * 256 + cv) = packbf(v00, v01);
                *(uint32_t*)(g_v + pg1 * 256 + cv) = packbf(v10, v11);
            }
        }
    }
}

// ---------------------------------------------------------------------------
// Kernel 3: E = QK^T + fused exp(E-40) -> P, row sums.
// CHANGED vs R9: single product (hi x hi only; precision validated in R10),
// and row sums from fp32 accumulators via shfl + smem red + 1 atomic/row.
// Tile layout/loads identical to R9.
// ---------------------------------------------------------------------------
__global__ __launch_bounds__(256, 2) void egemm_kernel()
{
    __shared__ __align__(16) __nv_bfloat16 esm[2 * 128 * 72];
    __shared__ float red[128][4];
    __nv_bfloat16* sQ = esm;
    __nv_bfloat16* sK = esm + 128 * 72;
    const int m0 = blockIdx.x * 128, n0 = blockIdx.y * 128, b = blockIdx.z;
    const int t = threadIdx.x, lane = t & 31, wid = t >> 5;
    const int warp_r = wid >> 2, warp_c = wid & 3;

    {
        const uint4* qs = (const uint4*)(g_q64 + ((size_t)(b * NPIX + n0)) * 64);
        const uint4* ks = (const uint4*)(g_k64 + ((size_t)(b * NPIX + m0)) * 64);
        uint4* q4 = (uint4*)sQ;
        uint4* k4 = (uint4*)sK;
        #pragma unroll
        for (int i = 0; i < 4; i++) {
            int idx = i * 256 + t;
            int row = idx >> 3, ch = idx & 7;
            q4[row * 9 + ch] = qs[idx];
            k4[row * 9 + ch] = ks[idx];
        }
    }
    __syncthreads();

    float acc[4][4][4];
    #pragma unroll
    for (int mi = 0; mi < 4; mi++)
        #pragma unroll
        for (int ni = 0; ni < 4; ni++)
            #pragma unroll
            for (int i = 0; i < 4; i++) acc[mi][ni][i] = 0.0f;

    // single product: qh . kh  (layout identical to R9, aoff=boff=0)
    #pragma unroll
    for (int k16 = 0; k16 < 2; k16++) {
        const int kb = k16 * 16;
        uint32_t A[4][4];
        #pragma unroll
        for (int mi = 0; mi < 4; mi++)
            ldsm4(A[mi], s2u(sQ + (warp_r * 64 + mi * 16 + (lane & 15)) * 72
                                + kb + ((lane >> 4) << 3)));
        uint32_t Bm[2][4];
        #pragma unroll
        for (int nj = 0; nj < 2; nj++)
            ldsm4(Bm[nj], s2u(sK + (warp_c * 32 + nj * 16 + (lane & 15)) * 72
                                 + kb + ((lane >> 4) << 3)));
        #pragma unroll
        for (int mi = 0; mi < 4; mi++)
            #pragma unroll
            for (int ni = 0; ni < 4; ni++) {
                int nj = ni >> 1, s = ni & 1;
                mma16816(acc[mi][ni], A[mi], Bm[nj][s], Bm[nj][s + 2]);
            }
    }
    __syncthreads();   // tiles dead; reuse esm as P stage (stride 136)

    __nv_bfloat16* sS = esm;
    #pragma unroll
    for (int mi = 0; mi < 4; mi++) {
        int r0 = warp_r * 64 + mi * 16 + (lane >> 2);
        float s0 = 0.0f, s1 = 0.0f;
        #pragma unroll
        for (int ni = 0; ni < 4; ni++) {
            int c = warp_c * 32 + ni * 8 + (lane & 3) * 2;
            float p00 = __expf(acc[mi][ni][0] - 40.0f);
            float p01 = __expf(acc[mi][ni][1] - 40.0f);
            float p10 = __expf(acc[mi][ni][2] - 40.0f);
            float p11 = __expf(acc[mi][ni][3] - 40.0f);
            s0 += p00 + p01;
            s1 += p10 + p11;
            *(uint32_t*)(sS + r0 * 136 + c)       = packbf(p00, p01);
            *(uint32_t*)(sS + (r0 + 8) * 136 + c) = packbf(p10, p11);
        }
        // reduce over the 4 lanes sharing each row
        s0 += __shfl_xor_sync(0xffffffffu, s0, 1);
        s0 += __shfl_xor_sync(0xffffffffu, s0, 2);
        s1 += __shfl_xor_sync(0xffffffffu, s1, 1);
        s1 += __shfl_xor_sync(0xffffffffu, s1, 2);
        if ((lane & 3) == 0) {
            red[r0][warp_c]     = s0;
            red[r0 + 8][warp_c] = s1;
        }
    }
    __syncthreads();

    // coalesced P write (pure copy) + one atomic per row
    #pragma unroll
    for (int pass = 0; pass < 4; pass++) {
        int row = pass * 32 + (t >> 3), ch = t & 7;
        const uint4* srow = (const uint4*)(sS + row * 136);
        uint4* drow = (uint4*)(g_P + ((size_t)(b * NPIX + n0 + row)) * NPIX + m0);
        drow[ch * 2]     = srow[ch * 2];
        drow[ch * 2 + 1] = srow[ch * 2 + 1];
        if (ch == 0)
            atomicAdd(&g_l[b * NPIX + n0 + row],
                      red[row][0] + red[row][1] + red[row][2] + red[row][3]);
    }
}

// ---------------------------------------------------------------------------
// Kernel 4: O = P @ V (bf16 HMMA, cp.async double buffer), output [b][c][n].
// (unchanged from R9)
// ---------------------------------------------------------------------------
#define PBUF (128 * 72)
#define VBUF (64 * 264)
#define BUFBF (PBUF + VBUF)
#define PV_SMEM (2 * BUFBF * 2)

__global__ __launch_bounds__(256, 1) void pv_kernel()
{
    extern __shared__ __align__(16) __nv_bfloat16 pvs[];
    const int n0 = blockIdx.x * 128, b = blockIdx.y;
    const int t = threadIdx.x, lane = t & 31, wid = t >> 5;
    const int warp_r = wid >> 2, warp_c = wid & 3;

    const __nv_bfloat16* pbase = g_P + ((size_t)(b * NPIX + n0)) * NPIX;
    const __nv_bfloat16* vbase = g_v + (size_t)b * NPIX * CDIM;

    float acc[4][8][4];
    #pragma unroll
    for (int mi = 0; mi < 4; mi++)
        #pragma unroll
        for (int ni = 0; ni < 8; ni++)
            #pragma unroll
            for (int i = 0; i < 4; i++) acc[mi][ni][i] = 0.0f;

    auto issue = [&](int ch, int s) {
        __nv_bfloat16* sP = pvs + s * BUFBF;
        __nv_bfloat16* sV = sP + PBUF;
        #pragma unroll
        for (int i = 0; i < 4; i++) {
            int idx = i * 256 + t;
            int row = idx >> 3, c8 = idx & 7;
            cpa16(s2u(sP + row * 72 + c8 * 8),
                  pbase + (size_t)row * NPIX + ch * 64 + c8 * 8);
        }
        #pragma unroll
        for (int i = 0; i < 8; i++) {
            int idx = i * 256 + t;
            int row = idx >> 5, c8 = idx & 31;
            cpa16(s2u(sV + row * 264 + c8 * 8),
                  vbase + (size_t)(ch * 64 + row) * CDIM + c8 * 8);
        }
        CP_COMMIT();
    };

    issue(0, 0);
    for (int ch = 0; ch < 64; ch++) {
        if (ch < 63) issue(ch + 1, (ch + 1) & 1);
        if (ch < 63) asm volatile("cp.async.wait_group 1;" ::: "memory");
        else         asm volatile("cp.async.wait_group 0;" ::: "memory");
        __syncthreads();
        __nv_bfloat16* sP = pvs + (ch & 1) * BUFBF;
        __nv_bfloat16* sV = sP + PBUF;
        #pragma unroll
        for (int k16 = 0; k16 < 4; k16++) {
            const int kb = k16 * 16;
            uint32_t A[4][4];
            #pragma unroll
            for (int mi = 0; mi < 4; mi++)
                ldsm4(A[mi], s2u(sP + (warp_r * 64 + mi * 16 + (lane & 15)) * 72
                                    + kb + ((lane >> 4) << 3)));
            uint32_t Bm[4][4];
            #pragma unroll
            for (int nj = 0; nj < 4; nj++) {
                int k = kb + (lane & 7) + ((lane >> 4) << 3);
                int n = warp_c * 64 + nj * 16 + ((lane >> 3) & 1) * 8;
                ldsm4t(Bm[nj], s2u(sV + k * 264 + n));
            }
            #pragma unroll
            for (int mi = 0; mi < 4; mi++)
                #pragma unroll
                for (int ni = 0; ni < 8; ni++) {
                    int nj = ni >> 1, s = ni & 1;
                    mma16816(acc[mi][ni], A[mi], Bm[nj][s], Bm[nj][s + 2]);
                }
        }
        __syncthreads();
    }

    // epilogue: normalize, transpose via smem, write g_o[b][c][n] coalesced
    float* sT = (float*)pvs;   // [128 c][140 px-stride]
    #pragma unroll
    for (int half = 0; half < 2; half++) {
        if ((warp_c >> 1) == half) {
            #pragma unroll
            for (int mi = 0; mi < 4; mi++) {
                int px0 = warp_r * 64 + mi * 16 + (lane >> 2);
                float li0 = 1.0f / g_l[b * NPIX + n0 + px0];
                float li1 = 1.0f / g_l[b * NPIX + n0 + px0 + 8];
                #pragma unroll
                for (int ni = 0; ni < 8; ni++) {
                    int cl = (warp_c & 1) * 64 + ni * 8 + (lane & 3) * 2;
                    sT[cl * 140 + px0]           = acc[mi][ni][0] * li0;
                    sT[(cl + 1) * 140 + px0]     = acc[mi][ni][1] * li0;
                    sT[cl * 140 + px0 + 8]       = acc[mi][ni][2] * li1;
                    sT[(cl + 1) * 140 + px0 + 8] = acc[mi][ni][3] * li1;
                }
            }
        }
        __syncthreads();
        #pragma unroll
        for (int i = 0; i < 16; i++) {
            int f4 = i * 256 + t;
            int c = f4 >> 5, col = (f4 & 31) * 4;
            float4 v = *(float4*)(sT + c * 140 + col);
            *(float4*)(g_o + ((size_t)(b * 256 + half * 128 + c)) * 4096 + n0 + col) = v;
        }
        __syncthreads();
    }
}

// ---------------------------------------------------------------------------
// Kernel 5: epilogue gamma*O + xp, depth-to-space (g_o reads coalesced).
// ---------------------------------------------------------------------------
__global__ __launch_bounds__(256) void epi_kernel(
    const float* __restrict__ x, const float* __restrict__ gamma,
    float* __restrict__ out)
{
    int idx = blockIdx.x * 256 + threadIdx.x;
    int w = idx & 127, h = (idx >> 7) & 127, ci = (idx >> 14) & 63, b = idx >> 20;
    int CC = (w & 1) * 128 + (h & 1) * 64 + ci;
    int n = (h >> 1) * 64 + (w >> 1);
    out[idx] = __ldg(gamma) * g_o[((size_t)(b * 256 + CC)) * 4096 + n] + x[idx];
}

// ---------------------------------------------------------------------------
extern "C" void kernel_launch(void* const* d_in, const int* in_sizes, int n_in,
                              void* d_out, int out_size)
{
    const float* x     = (const float*)d_in[0];
    const float* wq    = (const float*)d_in[1];
    const float* bq    = (const float*)d_in[2];
    const float* wk    = (const float*)d_in[3];
    const float* bk    = (const float*)d_in[4];
    const float* wv    = (const float*)d_in[5];
    const float* bv    = (const float*)d_in[6];
    const float* gamma = (const float*)d_in[7];
    float* out = (float*)d_out;
    (void)in_sizes; (void)n_in; (void)out_size;

    cudaFuncSetAttribute(projgemm_kernel, cudaFuncAttributeMaxDynamicSharedMemorySize, PG_SMEM);
    cudaFuncSetAttribute(pv_kernel,       cudaFuncAttributeMaxDynamicSharedMemorySize, PV_SMEM);

    wconv_kernel<<<80, 256>>>(wq, wk, wv);

    dim3 ggrid(2, 64, BATCH);
    gather_kernel<<<ggrid, 256>>>(x);

    dim3 pggrid(NPTOT / 128, 5);
    projgemm_kernel<<<pggrid, 256, PG_SMEM>>>(bq, bk, bv);

    dim3 egrid(NPIX / 128, NPIX / 128, BATCH);
    egemm_kernel<<<egrid, 256>>>();

    dim3 vgrid(NPIX / 128, BATCH);
    pv_kernel<<<vgrid, 256, PV_SMEM>>>();

    epi_kernel<<<(BATCH * 64 * 128 * 128) / 256, 256>>>(x, gamma, out);
}